// round 4
// baseline (speedup 1.0000x reference)
#include <cuda_runtime.h>
#include <cuda_fp16.h>
#include <cstdint>
#include <cstddef>

// ---------------------------------------------------------------------------
// Grouped SwiGLU FFN:  out = (silu(x@w1) * (x@w3^T)) @ w2^T   per expert
// E=8, T=1024, D=2048, H=4096, fp32 in/out.
// sm_103 baseline ISA only (no tcgen05 / no 'a' features): mma.sync HMMA path.
// ---------------------------------------------------------------------------
#define NE 8
#define NT 1024
#define ND 2048
#define NH 4096

static constexpr int BM = 128, BN = 256, BK = 32, STAGES = 4;
static constexpr int THREADS = 512;
// padded smem rows: 32 fp16 = 64 B data + 16 B pad = 80 B stride (bank-conflict free)
static constexpr uint32_t A_SM    = BM * 80;          // 10240 B
static constexpr uint32_t B_SM    = BN * 80;          // 20480 B
static constexpr uint32_t STAGE_B = A_SM + B_SM;      // 30720 B
static constexpr uint32_t SMEM_GEMM = STAGES * STAGE_B;  // 122880 B

// ---------------------------------------------------------------------------
// Scratch (__device__ bss — no runtime allocation)
// ---------------------------------------------------------------------------
__device__ __half g_x16[(size_t)NE * NT * ND];   //  32 MB  x fp16      [E,T,D]
__device__ __half g_w1t[(size_t)NE * NH * ND];   // 128 MB  w1^T fp16   [E,H,D]
__device__ __half g_w3h[(size_t)NE * NH * ND];   // 128 MB  w3 fp16     [E,H,D]
__device__ __half g_w2h[(size_t)NE * ND * NH];   // 128 MB  w2 fp16     [E,D,H]
__device__ __half g_u  [(size_t)NE * NT * NH];   //  64 MB  x@w1        [E,T,H]
__device__ __half g_g  [(size_t)NE * NT * NH];   //  64 MB  x@w3^T      [E,T,H]
__device__ __half g_act[(size_t)NE * NT * NH];   //  64 MB  silu(u)*g   [E,T,H]

// ---------------------------------------------------------------------------
// PTX helpers (baseline sm_80+ features only)
// ---------------------------------------------------------------------------
__device__ __forceinline__ uint32_t smem_u32(const void* p) {
    return (uint32_t)__cvta_generic_to_shared(p);
}

__device__ __forceinline__ void cp16(uint32_t dst, const void* src) {
    asm volatile("cp.async.cg.shared.global [%0], [%1], 16;" ::"r"(dst), "l"(src)
                 : "memory");
}
#define CP_COMMIT() asm volatile("cp.async.commit_group;" ::: "memory")
#define CP_WAIT2()  asm volatile("cp.async.wait_group 2;" ::: "memory")

__device__ __forceinline__ void ldm_x4(uint32_t* r, uint32_t addr) {
    asm volatile("ldmatrix.sync.aligned.m8n8.x4.shared.b16 {%0,%1,%2,%3}, [%4];"
                 : "=r"(r[0]), "=r"(r[1]), "=r"(r[2]), "=r"(r[3])
                 : "r"(addr));
}

__device__ __forceinline__ void mma16816(float* c, const uint32_t* a,
                                         uint32_t b0, uint32_t b1) {
    asm volatile(
        "mma.sync.aligned.m16n8k16.row.col.f32.f16.f16.f32 "
        "{%0,%1,%2,%3}, {%4,%5,%6,%7}, {%8,%9}, {%0,%1,%2,%3};"
        : "+f"(c[0]), "+f"(c[1]), "+f"(c[2]), "+f"(c[3])
        : "r"(a[0]), "r"(a[1]), "r"(a[2]), "r"(a[3]), "r"(b0), "r"(b1));
}

// ---------------------------------------------------------------------------
// fp32 -> fp16 conversion / transpose prep kernels
// ---------------------------------------------------------------------------
__device__ __forceinline__ void conv_body(const float* __restrict__ src,
                                          __half* __restrict__ dst) {
    size_t i = (size_t)blockIdx.x * blockDim.x + threadIdx.x;
    float4 v = reinterpret_cast<const float4*>(src)[i];
    reinterpret_cast<__half2*>(dst)[2 * i]     = __floats2half2_rn(v.x, v.y);
    reinterpret_cast<__half2*>(dst)[2 * i + 1] = __floats2half2_rn(v.z, v.w);
}
__global__ void k_conv_x (const float* __restrict__ s) { conv_body(s, g_x16); }
__global__ void k_conv_w2(const float* __restrict__ s) { conv_body(s, g_w2h); }
__global__ void k_conv_w3(const float* __restrict__ s) { conv_body(s, g_w3h); }

// w1 [E,D,H] fp32 -> g_w1t [E,H,D] fp16 (tiled transpose)
__global__ void k_tr_w1(const float* __restrict__ w1) {
    __shared__ float t[32][33];
    int e = blockIdx.z;
    int h0 = blockIdx.x * 32, d0 = blockIdx.y * 32;
    const float* src = w1 + ((size_t)e * ND + d0) * NH + h0;
#pragma unroll
    for (int i = 0; i < 4; ++i)
        t[threadIdx.y + 8 * i][threadIdx.x] =
            src[(size_t)(threadIdx.y + 8 * i) * NH + threadIdx.x];
    __syncthreads();
    __half* dst = g_w1t + ((size_t)e * NH + h0) * ND + d0;
#pragma unroll
    for (int i = 0; i < 4; ++i)
        dst[(size_t)(threadIdx.y + 8 * i) * ND + threadIdx.x] =
            __float2half(t[threadIdx.x][threadIdx.y + 8 * i]);
}

// ---------------------------------------------------------------------------
// GEMM: C[M=T, N=NTOT] = A[T, KTOT] @ B[NTOT, KTOT]^T   (both K-contiguous)
// 512 threads, 16 warps in 4x4 grid; warp tile 32x64 via m16n8k16.
// ---------------------------------------------------------------------------
template <int KTOT, int NTOT, bool F32OUT>
__global__ void __launch_bounds__(THREADS, 1)
k_gemm(const __half* __restrict__ Ab, const __half* __restrict__ Bb,
       void* __restrict__ Cb) {
    extern __shared__ __align__(128) char sm[];
    uint32_t base = smem_u32(sm);
    int tid = threadIdx.x, lane = tid & 31, wid = tid >> 5;
    int wm = wid >> 2, wn = wid & 3;
    int e = blockIdx.z;
    const __half* A = Ab + (size_t)e * NT * KTOT + (size_t)blockIdx.y * BM * KTOT;
    const __half* B = Bb + (size_t)e * NTOT * KTOT + (size_t)blockIdx.x * BN * KTOT;

    // per-thread cp.async coords: A = 512 16B chunks, B = 1024 chunks
    int ar = tid >> 2, ac = tid & 3;

    auto load = [&](int st, int kb) {
        uint32_t sa = base + (uint32_t)st * STAGE_B;
        const __half* Ak = A + kb * BK;
        cp16(sa + (uint32_t)(ar * 80 + ac * 16), Ak + (size_t)ar * KTOT + ac * 8);
        uint32_t sb = sa + A_SM;
        const __half* Bk = B + kb * BK;
#pragma unroll
        for (int i = 0; i < 2; ++i) {
            int id = tid + i * THREADS;
            int r = id >> 2, c = id & 3;
            cp16(sb + (uint32_t)(r * 80 + c * 16), Bk + (size_t)r * KTOT + c * 8);
        }
        CP_COMMIT();
    };

    load(0, 0);
    load(1, 1);
    load(2, 2);

    float c[2][8][4];
#pragma unroll
    for (int mi = 0; mi < 2; ++mi)
#pragma unroll
        for (int ni = 0; ni < 8; ++ni)
#pragma unroll
            for (int q = 0; q < 4; ++q) c[mi][ni][q] = 0.f;

    constexpr int KIT = KTOT / BK;
    // ldmatrix lane addressing (80 B row stride => conflict-free)
    uint32_t a_off = (uint32_t)((wm * 32 + (lane & 15)) * 80 + (lane >> 4) * 16);
    uint32_t b_off = A_SM +
        (uint32_t)((wn * 64 + ((lane >> 4) << 3) + (lane & 7)) * 80 +
                   ((lane >> 3) & 1) * 16);

    for (int k = 0; k < KIT; ++k) {
        CP_WAIT2();
        __syncthreads();
        if (k + 3 < KIT) load((k + 3) & 3, k + 3);
        else CP_COMMIT();

        uint32_t sa = base + (uint32_t)(k & 3) * STAGE_B;
#pragma unroll
        for (int ks = 0; ks < 2; ++ks) {
            uint32_t ra[2][4], rb[4][4];
#pragma unroll
            for (int mi = 0; mi < 2; ++mi)
                ldm_x4(ra[mi], sa + a_off + (uint32_t)(mi * 16 * 80 + ks * 32));
#pragma unroll
            for (int nj = 0; nj < 4; ++nj)
                ldm_x4(rb[nj], sa + b_off + (uint32_t)(nj * 16 * 80 + ks * 32));
#pragma unroll
            for (int mi = 0; mi < 2; ++mi)
#pragma unroll
                for (int ni = 0; ni < 8; ++ni)
                    mma16816(c[mi][ni], ra[mi],
                             rb[ni >> 1][(ni & 1) * 2], rb[ni >> 1][(ni & 1) * 2 + 1]);
        }
    }

    // epilogue
    int t0 = blockIdx.y * BM + wm * 32 + (lane >> 2);
    int n0 = blockIdx.x * BN + wn * 64 + (lane & 3) * 2;
    if (F32OUT) {
        float* C = (float*)Cb + (size_t)e * NT * NTOT;
#pragma unroll
        for (int mi = 0; mi < 2; ++mi)
#pragma unroll
            for (int ni = 0; ni < 8; ++ni) {
                int r = t0 + mi * 16, col = n0 + ni * 8;
                *reinterpret_cast<float2*>(C + (size_t)r * NTOT + col) =
                    make_float2(c[mi][ni][0], c[mi][ni][1]);
                *reinterpret_cast<float2*>(C + (size_t)(r + 8) * NTOT + col) =
                    make_float2(c[mi][ni][2], c[mi][ni][3]);
            }
    } else {
        __half* C = (__half*)Cb + (size_t)e * NT * NTOT;
#pragma unroll
        for (int mi = 0; mi < 2; ++mi)
#pragma unroll
            for (int ni = 0; ni < 8; ++ni) {
                int r = t0 + mi * 16, col = n0 + ni * 8;
                *reinterpret_cast<__half2*>(C + (size_t)r * NTOT + col) =
                    __floats2half2_rn(c[mi][ni][0], c[mi][ni][1]);
                *reinterpret_cast<__half2*>(C + (size_t)(r + 8) * NTOT + col) =
                    __floats2half2_rn(c[mi][ni][2], c[mi][ni][3]);
            }
    }
}

// ---------------------------------------------------------------------------
// act = silu(u) * g  (elementwise, half2)
// ---------------------------------------------------------------------------
__global__ void k_silu() {
    size_t i = (size_t)blockIdx.x * blockDim.x + threadIdx.x;
    float2 u = __half22float2(reinterpret_cast<const __half2*>(g_u)[i]);
    float2 g = __half22float2(reinterpret_cast<const __half2*>(g_g)[i]);
    float a0 = g.x * u.x / (1.f + __expf(-u.x));
    float a1 = g.y * u.y / (1.f + __expf(-u.y));
    reinterpret_cast<__half2*>(g_act)[i] = __floats2half2_rn(a0, a1);
}

// ---------------------------------------------------------------------------
// Launch (graph-capturable: kernel launches only)
// ---------------------------------------------------------------------------
extern "C" void kernel_launch(void* const* d_in, const int* in_sizes, int n_in,
                              void* d_out, int out_size) {
    const float* x  = (const float*)d_in[0];
    const float* w1 = (const float*)d_in[1];
    const float* w2 = (const float*)d_in[2];
    const float* w3 = (const float*)d_in[3];
    float* out = (float*)d_out;

    static bool attr_done = false;
    (void)attr_done;
    cudaFuncSetAttribute(k_gemm<ND, NH, false>,
                         cudaFuncAttributeMaxDynamicSharedMemorySize, SMEM_GEMM);
    cudaFuncSetAttribute(k_gemm<NH, ND, true>,
                         cudaFuncAttributeMaxDynamicSharedMemorySize, SMEM_GEMM);

    void *px16, *pw1t, *pw3h, *pw2h, *pu, *pg, *pact;
    cudaGetSymbolAddress(&px16, g_x16);
    cudaGetSymbolAddress(&pw1t, g_w1t);
    cudaGetSymbolAddress(&pw3h, g_w3h);
    cudaGetSymbolAddress(&pw2h, g_w2h);
    cudaGetSymbolAddress(&pu,   g_u);
    cudaGetSymbolAddress(&pg,   g_g);
    cudaGetSymbolAddress(&pact, g_act);

    // prep: fp32 -> fp16 (+ w1 transpose to K-major)
    k_conv_x <<<16384, 256>>>(x);                       // E*T*D/4/256
    k_conv_w3<<<65536, 256>>>(w3);                      // E*D*H/4/256
    k_conv_w2<<<65536, 256>>>(w2);
    k_tr_w1<<<dim3(NH / 32, ND / 32, NE), dim3(32, 8)>>>(w1);

    // u = x @ w1 ; g = x @ w3^T     (K = D = 2048, N = H = 4096)
    k_gemm<ND, NH, false><<<dim3(NH / BN, NT / BM, NE), THREADS, SMEM_GEMM>>>(
        (const __half*)px16, (const __half*)pw1t, pu);
    k_gemm<ND, NH, false><<<dim3(NH / BN, NT / BM, NE), THREADS, SMEM_GEMM>>>(
        (const __half*)px16, (const __half*)pw3h, pg);

    // act = silu(u) * g
    k_silu<<<65536, 256>>>();                           // E*T*H/2/256

    // out = act @ w2^T              (K = H = 4096, N = D = 2048, fp32 out)
    k_gemm<NH, ND, true><<<dim3(ND / BN, NT / BM, NE), THREADS, SMEM_GEMM>>>(
        (const __half*)pact, (const __half*)pw2h, out);
}

// round 5
// speedup vs baseline: 1.1764x; 1.1764x over previous
#include <cuda_runtime.h>
#include <cuda_fp16.h>
#include <cstdint>
#include <cstddef>

// ---------------------------------------------------------------------------
// Grouped SwiGLU FFN:  out = (silu(x@w1) * (x@w3^T)) @ w2^T   per expert
// E=8, T=1024, D=2048, H=4096, fp32 in/out.  sm_103 baseline ISA (mma.sync).
// ---------------------------------------------------------------------------
#define NE 8
#define NT 1024
#define ND 2048
#define NH 4096

static constexpr int BM = 128, BK = 64, STAGES = 3;
static constexpr int THREADS = 512;
// padded smem rows: 64 fp16 = 128 B data + 16 B pad = 144 B stride.
// ldmatrix conflict-free: (144/16) = 9, 9*r mod 8 = r mod 8 -> distinct banksets.
static constexpr uint32_t SR     = 144;
static constexpr uint32_t T128   = BM * SR;          // 18432 B per 128-row tile
// fused phase-1 stage: A(128) + B1(128) + B2(128)
static constexpr uint32_t STAGE1 = 3 * T128;         // 55296
static constexpr uint32_t SMEM1  = STAGES * STAGE1;  // 165888
// phase-2 stage: A(128) + B(256)
static constexpr uint32_t STAGE2 = 3 * T128;         // 55296
static constexpr uint32_t SMEM2  = STAGES * STAGE2;  // 165888

// ---------------------------------------------------------------------------
// Scratch (__device__ bss — no runtime allocation)
// ---------------------------------------------------------------------------
__device__ __half g_x16[(size_t)NE * NT * ND];   //  32 MB  x fp16      [E,T,D]
__device__ __half g_w1t[(size_t)NE * NH * ND];   // 128 MB  w1^T fp16   [E,H,D]
__device__ __half g_w3h[(size_t)NE * NH * ND];   // 128 MB  w3 fp16     [E,H,D]
__device__ __half g_w2h[(size_t)NE * ND * NH];   // 128 MB  w2 fp16     [E,D,H]
__device__ __half g_act[(size_t)NE * NT * NH];   //  64 MB  silu(u)*g   [E,T,H]

// ---------------------------------------------------------------------------
// PTX helpers (baseline sm_80+ features only)
// ---------------------------------------------------------------------------
__device__ __forceinline__ uint32_t smem_u32(const void* p) {
    return (uint32_t)__cvta_generic_to_shared(p);
}

__device__ __forceinline__ void cp16(uint32_t dst, const void* src) {
    asm volatile("cp.async.cg.shared.global [%0], [%1], 16;" ::"r"(dst), "l"(src)
                 : "memory");
}
#define CP_COMMIT() asm volatile("cp.async.commit_group;" ::: "memory")
#define CP_WAIT1()  asm volatile("cp.async.wait_group 1;" ::: "memory")

__device__ __forceinline__ void ldm_x4(uint32_t* r, uint32_t addr) {
    asm volatile("ldmatrix.sync.aligned.m8n8.x4.shared.b16 {%0,%1,%2,%3}, [%4];"
                 : "=r"(r[0]), "=r"(r[1]), "=r"(r[2]), "=r"(r[3])
                 : "r"(addr));
}

__device__ __forceinline__ void mma16816(float* c, const uint32_t* a,
                                         uint32_t b0, uint32_t b1) {
    asm volatile(
        "mma.sync.aligned.m16n8k16.row.col.f32.f16.f16.f32 "
        "{%0,%1,%2,%3}, {%4,%5,%6,%7}, {%8,%9}, {%0,%1,%2,%3};"
        : "+f"(c[0]), "+f"(c[1]), "+f"(c[2]), "+f"(c[3])
        : "r"(a[0]), "r"(a[1]), "r"(a[2]), "r"(a[3]), "r"(b0), "r"(b1));
}

// ---------------------------------------------------------------------------
// fp32 -> fp16 conversion / transpose prep kernels
// ---------------------------------------------------------------------------
__device__ __forceinline__ void conv_body(const float* __restrict__ src,
                                          __half* __restrict__ dst) {
    size_t i = (size_t)blockIdx.x * blockDim.x + threadIdx.x;
    float4 v = reinterpret_cast<const float4*>(src)[i];
    reinterpret_cast<__half2*>(dst)[2 * i]     = __floats2half2_rn(v.x, v.y);
    reinterpret_cast<__half2*>(dst)[2 * i + 1] = __floats2half2_rn(v.z, v.w);
}
__global__ void k_conv_x (const float* __restrict__ s) { conv_body(s, g_x16); }
__global__ void k_conv_w2(const float* __restrict__ s) { conv_body(s, g_w2h); }
__global__ void k_conv_w3(const float* __restrict__ s) { conv_body(s, g_w3h); }

// w1 [E,D,H] fp32 -> g_w1t [E,H,D] fp16 (tiled transpose)
__global__ void k_tr_w1(const float* __restrict__ w1) {
    __shared__ float t[32][33];
    int e = blockIdx.z;
    int h0 = blockIdx.x * 32, d0 = blockIdx.y * 32;
    const float* src = w1 + ((size_t)e * ND + d0) * NH + h0;
#pragma unroll
    for (int i = 0; i < 4; ++i)
        t[threadIdx.y + 8 * i][threadIdx.x] =
            src[(size_t)(threadIdx.y + 8 * i) * NH + threadIdx.x];
    __syncthreads();
    __half* dst = g_w1t + ((size_t)e * NH + h0) * ND + d0;
#pragma unroll
    for (int i = 0; i < 4; ++i)
        dst[(size_t)(threadIdx.y + 8 * i) * ND + threadIdx.x] =
            __float2half(t[threadIdx.x][threadIdx.y + 8 * i]);
}

// ---------------------------------------------------------------------------
// Phase 1 (fused): u = x@w1t^T, g = x@w3^T, act = silu(u)*g  -> g_act fp16
// BM=128, 128 N-cols per B operand. 16 warps (4x4); warp tile 32x32 per B.
// ---------------------------------------------------------------------------
__global__ void __launch_bounds__(THREADS, 1) k_ffn1() {
    extern __shared__ __align__(128) char sm[];
    uint32_t base = smem_u32(sm);
    int tid = threadIdx.x, lane = tid & 31, wid = tid >> 5;
    int wm = wid >> 2, wn = wid & 3;
    int e = blockIdx.z;
    constexpr int KIT = ND / BK;  // 32

    const __half* A  = g_x16 + ((size_t)e * NT + blockIdx.y * BM) * ND;
    const __half* B1 = g_w1t + ((size_t)e * NH + blockIdx.x * 128) * ND;
    const __half* B2 = g_w3h + ((size_t)e * NH + blockIdx.x * 128) * ND;

    auto load = [&](int st, int kb) {
        uint32_t s0 = base + (uint32_t)st * STAGE1;
        int ko = kb * BK;
#pragma unroll
        for (int i = 0; i < 2; ++i) {
            int id = tid + i * THREADS;           // 1024 chunks per 128-row tile
            int r = id >> 3, c = id & 7;
            uint32_t so = (uint32_t)(r * SR + c * 16);
            size_t  go = (size_t)r * ND + ko + c * 8;
            cp16(s0 + so,             A  + go);
            cp16(s0 + T128 + so,      B1 + go);
            cp16(s0 + 2 * T128 + so,  B2 + go);
        }
        CP_COMMIT();
    };

    load(0, 0);
    load(1, 1);

    float c[2][2][4][4];                          // [B][mi][ni][frag]
#pragma unroll
    for (int b = 0; b < 2; ++b)
#pragma unroll
        for (int mi = 0; mi < 2; ++mi)
#pragma unroll
            for (int ni = 0; ni < 4; ++ni)
#pragma unroll
                for (int q = 0; q < 4; ++q) c[b][mi][ni][q] = 0.f;

    uint32_t a_off = (uint32_t)((wm * 32 + (lane & 15)) * SR + (lane >> 4) * 16);
    uint32_t b_off = (uint32_t)((wn * 32 + ((lane >> 4) << 3) + (lane & 7)) * SR +
                                ((lane >> 3) & 1) * 16);

#pragma unroll 1
    for (int k = 0; k < KIT; ++k) {
        CP_WAIT1();
        __syncthreads();
        if (k + 2 < KIT) load((k + 2) % 3, k + 2);
        else CP_COMMIT();

        uint32_t s0 = base + (uint32_t)(k % 3) * STAGE1;
#pragma unroll
        for (int ks = 0; ks < 4; ++ks) {          // 4 x K=16 steps
            uint32_t ra[2][4], rb[2][2][4];
#pragma unroll
            for (int mi = 0; mi < 2; ++mi)
                ldm_x4(ra[mi], s0 + a_off + (uint32_t)(mi * 16 * SR + ks * 32));
#pragma unroll
            for (int b = 0; b < 2; ++b)
#pragma unroll
                for (int nj = 0; nj < 2; ++nj)
                    ldm_x4(rb[b][nj], s0 + (uint32_t)((b + 1) * T128) + b_off +
                                      (uint32_t)(nj * 16 * SR + ks * 32));
#pragma unroll
            for (int b = 0; b < 2; ++b)
#pragma unroll
                for (int mi = 0; mi < 2; ++mi)
#pragma unroll
                    for (int ni = 0; ni < 4; ++ni)
                        mma16816(c[b][mi][ni], ra[mi],
                                 rb[b][ni >> 1][(ni & 1) * 2],
                                 rb[b][ni >> 1][(ni & 1) * 2 + 1]);
        }
    }

    // fused SiLU-gate epilogue -> g_act fp16
    int t0 = blockIdx.y * BM + wm * 32 + (lane >> 2);
    int h0 = blockIdx.x * 128 + wn * 32 + (lane & 3) * 2;
    __half* dst = g_act + (size_t)e * NT * NH;
#pragma unroll
    for (int mi = 0; mi < 2; ++mi)
#pragma unroll
        for (int ni = 0; ni < 4; ++ni) {
            int r = t0 + mi * 16, col = h0 + ni * 8;
            float* u = c[0][mi][ni];
            float* g = c[1][mi][ni];
            float a0 = g[0] * u[0] / (1.f + __expf(-u[0]));
            float a1 = g[1] * u[1] / (1.f + __expf(-u[1]));
            float a2 = g[2] * u[2] / (1.f + __expf(-u[2]));
            float a3 = g[3] * u[3] / (1.f + __expf(-u[3]));
            *reinterpret_cast<__half2*>(dst + (size_t)r * NH + col) =
                __floats2half2_rn(a0, a1);
            *reinterpret_cast<__half2*>(dst + (size_t)(r + 8) * NH + col) =
                __floats2half2_rn(a2, a3);
        }
}

// ---------------------------------------------------------------------------
// Phase 2: out = act @ w2^T   (K=4096, N=2048, fp32 out)
// BM=128, BN=256. 16 warps (4x4); warp tile 32x64.
// ---------------------------------------------------------------------------
__global__ void __launch_bounds__(THREADS, 1) k_ffn2(float* __restrict__ out) {
    extern __shared__ __align__(128) char sm[];
    uint32_t base = smem_u32(sm);
    int tid = threadIdx.x, lane = tid & 31, wid = tid >> 5;
    int wm = wid >> 2, wn = wid & 3;
    int e = blockIdx.z;
    constexpr int KIT = NH / BK;  // 64
    constexpr uint32_t A_SM = T128;

    const __half* A = g_act + ((size_t)e * NT + blockIdx.y * BM) * NH;
    const __half* B = g_w2h + ((size_t)e * ND + blockIdx.x * 256) * NH;

    auto load = [&](int st, int kb) {
        uint32_t s0 = base + (uint32_t)st * STAGE2;
        int ko = kb * BK;
#pragma unroll
        for (int i = 0; i < 2; ++i) {             // A: 1024 chunks
            int id = tid + i * THREADS;
            int r = id >> 3, c = id & 7;
            cp16(s0 + (uint32_t)(r * SR + c * 16), A + (size_t)r * NH + ko + c * 8);
        }
#pragma unroll
        for (int i = 0; i < 4; ++i) {             // B: 2048 chunks (256 rows)
            int id = tid + i * THREADS;
            int r = id >> 3, c = id & 7;
            cp16(s0 + A_SM + (uint32_t)(r * SR + c * 16),
                 B + (size_t)r * NH + ko + c * 8);
        }
        CP_COMMIT();
    };

    load(0, 0);
    load(1, 1);

    float c[2][8][4];
#pragma unroll
    for (int mi = 0; mi < 2; ++mi)
#pragma unroll
        for (int ni = 0; ni < 8; ++ni)
#pragma unroll
            for (int q = 0; q < 4; ++q) c[mi][ni][q] = 0.f;

    uint32_t a_off = (uint32_t)((wm * 32 + (lane & 15)) * SR + (lane >> 4) * 16);
    uint32_t b_off = A_SM +
        (uint32_t)((wn * 64 + ((lane >> 4) << 3) + (lane & 7)) * SR +
                   ((lane >> 3) & 1) * 16);

#pragma unroll 1
    for (int k = 0; k < KIT; ++k) {
        CP_WAIT1();
        __syncthreads();
        if (k + 2 < KIT) load((k + 2) % 3, k + 2);
        else CP_COMMIT();

        uint32_t s0 = base + (uint32_t)(k % 3) * STAGE2;
#pragma unroll
        for (int ks = 0; ks < 4; ++ks) {
            uint32_t ra[2][4], rb[4][4];
#pragma unroll
            for (int mi = 0; mi < 2; ++mi)
                ldm_x4(ra[mi], s0 + a_off + (uint32_t)(mi * 16 * SR + ks * 32));
#pragma unroll
            for (int nj = 0; nj < 4; ++nj)
                ldm_x4(rb[nj], s0 + b_off + (uint32_t)(nj * 16 * SR + ks * 32));
#pragma unroll
            for (int mi = 0; mi < 2; ++mi)
#pragma unroll
                for (int ni = 0; ni < 8; ++ni)
                    mma16816(c[mi][ni], ra[mi],
                             rb[ni >> 1][(ni & 1) * 2], rb[ni >> 1][(ni & 1) * 2 + 1]);
        }
    }

    int t0 = blockIdx.y * BM + wm * 32 + (lane >> 2);
    int n0 = blockIdx.x * 256 + wn * 64 + (lane & 3) * 2;
    float* C = out + (size_t)e * NT * ND;
#pragma unroll
    for (int mi = 0; mi < 2; ++mi)
#pragma unroll
        for (int ni = 0; ni < 8; ++ni) {
            int r = t0 + mi * 16, col = n0 + ni * 8;
            *reinterpret_cast<float2*>(C + (size_t)r * ND + col) =
                make_float2(c[mi][ni][0], c[mi][ni][1]);
            *reinterpret_cast<float2*>(C + (size_t)(r + 8) * ND + col) =
                make_float2(c[mi][ni][2], c[mi][ni][3]);
        }
}

// ---------------------------------------------------------------------------
// Launch (graph-capturable: kernel launches only)
// ---------------------------------------------------------------------------
extern "C" void kernel_launch(void* const* d_in, const int* in_sizes, int n_in,
                              void* d_out, int out_size) {
    const float* x  = (const float*)d_in[0];
    const float* w1 = (const float*)d_in[1];
    const float* w2 = (const float*)d_in[2];
    const float* w3 = (const float*)d_in[3];
    float* out = (float*)d_out;

    cudaFuncSetAttribute(k_ffn1, cudaFuncAttributeMaxDynamicSharedMemorySize, SMEM1);
    cudaFuncSetAttribute(k_ffn2, cudaFuncAttributeMaxDynamicSharedMemorySize, SMEM2);

    // prep: fp32 -> fp16 (+ w1 transpose to K-major)
    k_conv_x <<<16384, 256>>>(x);                       // E*T*D/4/256
    k_conv_w3<<<65536, 256>>>(w3);                      // E*D*H/4/256
    k_conv_w2<<<65536, 256>>>(w2);
    k_tr_w1<<<dim3(NH / 32, ND / 32, NE), dim3(32, 8)>>>(w1);

    // fused up+gate+silu  (K=D=2048, dual N=128 operands covering H)
    k_ffn1<<<dim3(NH / 128, NT / BM, NE), THREADS, SMEM1>>>();

    // down-proj           (K=H=4096, N=D=2048, fp32 out)
    k_ffn2<<<dim3(ND / 256, NT / BM, NE), THREADS, SMEM2>>>(out);
}

// round 6
// speedup vs baseline: 1.1931x; 1.0142x over previous
#include <cuda_runtime.h>
#include <cuda_fp16.h>
#include <cstdint>
#include <cstddef>

// ---------------------------------------------------------------------------
// Grouped SwiGLU FFN:  out = (silu(x@w1) * (x@w3^T)) @ w2^T   per expert
// E=8, T=1024, D=2048, H=4096, fp32 in/out.  sm_103 baseline ISA (mma.sync).
// ---------------------------------------------------------------------------
#define NE 8
#define NT 1024
#define ND 2048
#define NH 4096

static constexpr int BM = 128, BK = 64, STAGES = 4;
static constexpr int THREADS = 512;
// padded smem rows: 64 fp16 = 128 B data + 16 B pad = 144 B stride.
static constexpr uint32_t SR     = 144;
static constexpr uint32_t T128   = BM * SR;          // 18432 B per 128-row tile
static constexpr uint32_t STAGE1 = 3 * T128;         // A + B1 + B2      = 55296
static constexpr uint32_t SMEM1  = STAGES * STAGE1;  // 221184
static constexpr uint32_t STAGE2 = 3 * T128;         // A + B(256 rows)  = 55296
static constexpr uint32_t SMEM2  = STAGES * STAGE2;  // 221184

// ---------------------------------------------------------------------------
// Scratch (__device__ bss — no runtime allocation)
// ---------------------------------------------------------------------------
__device__ __half g_x16[(size_t)NE * NT * ND];   //  32 MB  x fp16      [E,T,D]
__device__ __half g_w1t[(size_t)NE * NH * ND];   // 128 MB  w1^T fp16   [E,H,D]
__device__ __half g_w3h[(size_t)NE * NH * ND];   // 128 MB  w3 fp16     [E,H,D]
__device__ __half g_w2h[(size_t)NE * ND * NH];   // 128 MB  w2 fp16     [E,D,H]
__device__ __half g_act[(size_t)NE * NT * NH];   //  64 MB  silu(u)*g   [E,T,H]

// ---------------------------------------------------------------------------
// PTX helpers (baseline sm_80+ features only)
// ---------------------------------------------------------------------------
__device__ __forceinline__ uint32_t smem_u32(const void* p) {
    return (uint32_t)__cvta_generic_to_shared(p);
}

__device__ __forceinline__ void cp16(uint32_t dst, const void* src) {
    asm volatile("cp.async.cg.shared.global [%0], [%1], 16;" ::"r"(dst), "l"(src)
                 : "memory");
}
#define CP_COMMIT() asm volatile("cp.async.commit_group;" ::: "memory")
#define CP_WAIT2()  asm volatile("cp.async.wait_group 2;" ::: "memory")

__device__ __forceinline__ void ldm_x4(uint32_t* r, uint32_t addr) {
    asm volatile("ldmatrix.sync.aligned.m8n8.x4.shared.b16 {%0,%1,%2,%3}, [%4];"
                 : "=r"(r[0]), "=r"(r[1]), "=r"(r[2]), "=r"(r[3])
                 : "r"(addr));
}

__device__ __forceinline__ void mma16816(float* c, const uint32_t* a,
                                         uint32_t b0, uint32_t b1) {
    asm volatile(
        "mma.sync.aligned.m16n8k16.row.col.f32.f16.f16.f32 "
        "{%0,%1,%2,%3}, {%4,%5,%6,%7}, {%8,%9}, {%0,%1,%2,%3};"
        : "+f"(c[0]), "+f"(c[1]), "+f"(c[2]), "+f"(c[3])
        : "r"(a[0]), "r"(a[1]), "r"(a[2]), "r"(a[3]), "r"(b0), "r"(b1));
}

// ---------------------------------------------------------------------------
// fp32 -> fp16 conversion / transpose prep kernels
// ---------------------------------------------------------------------------
__device__ __forceinline__ void conv_body(const float* __restrict__ src,
                                          __half* __restrict__ dst) {
    size_t i = (size_t)blockIdx.x * blockDim.x + threadIdx.x;
    float4 v = reinterpret_cast<const float4*>(src)[i];
    reinterpret_cast<__half2*>(dst)[2 * i]     = __floats2half2_rn(v.x, v.y);
    reinterpret_cast<__half2*>(dst)[2 * i + 1] = __floats2half2_rn(v.z, v.w);
}
__global__ void k_conv_x (const float* __restrict__ s) { conv_body(s, g_x16); }
__global__ void k_conv_w2(const float* __restrict__ s) { conv_body(s, g_w2h); }
__global__ void k_conv_w3(const float* __restrict__ s) { conv_body(s, g_w3h); }

// w1 [E,D,H] fp32 -> g_w1t [E,H,D] fp16, 64x64 tiles, 16B-wide ld/st
__global__ void __launch_bounds__(256) k_tr_w1(const float* __restrict__ w1) {
    __shared__ float t[64][65];
    int e = blockIdx.z, tid = threadIdx.x;
    int h0 = blockIdx.x * 64, d0 = blockIdx.y * 64;
    const float* src = w1 + ((size_t)e * ND + d0) * NH + h0;
#pragma unroll
    for (int i = 0; i < 4; ++i) {                     // 1024 float4 loads
        int u = tid + i * 256;
        int r = u >> 4, c4 = u & 15;
        float4 v = *reinterpret_cast<const float4*>(src + (size_t)r * NH + c4 * 4);
        t[r][c4 * 4 + 0] = v.x; t[r][c4 * 4 + 1] = v.y;
        t[r][c4 * 4 + 2] = v.z; t[r][c4 * 4 + 3] = v.w;
    }
    __syncthreads();
    __half* dst = g_w1t + ((size_t)e * NH + h0) * ND + d0;
#pragma unroll
    for (int i = 0; i < 2; ++i) {                     // 512 16B stores
        int u = tid + i * 256;
        int hr = u >> 3, dc = (u & 7) * 8;
        __half2 h2[4];
#pragma unroll
        for (int j = 0; j < 4; ++j)
            h2[j] = __floats2half2_rn(t[dc + 2 * j][hr], t[dc + 2 * j + 1][hr]);
        *reinterpret_cast<uint4*>(dst + (size_t)hr * ND + dc) =
            *reinterpret_cast<uint4*>(h2);
    }
}

// ---------------------------------------------------------------------------
// Phase 1 (fused): u = x@w1t^T, g = x@w3^T, act = silu(u)*g  -> g_act fp16
// grid (M=8, N=32, E): x = M so concurrent CTAs share weight tiles via L2.
// ---------------------------------------------------------------------------
__global__ void __launch_bounds__(THREADS, 1) k_ffn1() {
    extern __shared__ __align__(128) char sm[];
    uint32_t base = smem_u32(sm);
    int tid = threadIdx.x, lane = tid & 31, wid = tid >> 5;
    int wm = wid >> 2, wn = wid & 3;
    int e = blockIdx.z;
    constexpr int KIT = ND / BK;  // 32

    const __half* A  = g_x16 + ((size_t)e * NT + blockIdx.x * BM) * ND;
    const __half* B1 = g_w1t + ((size_t)e * NH + blockIdx.y * 128) * ND;
    const __half* B2 = g_w3h + ((size_t)e * NH + blockIdx.y * 128) * ND;

    auto load = [&](int st, int kb) {
        uint32_t s0 = base + (uint32_t)st * STAGE1;
        int ko = kb * BK;
#pragma unroll
        for (int i = 0; i < 2; ++i) {
            int id = tid + i * THREADS;           // 1024 chunks per 128-row tile
            int r = id >> 3, c = id & 7;
            uint32_t so = (uint32_t)(r * SR + c * 16);
            size_t  go = (size_t)r * ND + ko + c * 8;
            cp16(s0 + so,             A  + go);
            cp16(s0 + T128 + so,      B1 + go);
            cp16(s0 + 2 * T128 + so,  B2 + go);
        }
        CP_COMMIT();
    };

    load(0, 0);
    load(1, 1);
    load(2, 2);

    float c[2][2][4][4];                          // [B][mi][ni][frag]
#pragma unroll
    for (int b = 0; b < 2; ++b)
#pragma unroll
        for (int mi = 0; mi < 2; ++mi)
#pragma unroll
            for (int ni = 0; ni < 4; ++ni)
#pragma unroll
                for (int q = 0; q < 4; ++q) c[b][mi][ni][q] = 0.f;

    uint32_t a_off = (uint32_t)((wm * 32 + (lane & 15)) * SR + (lane >> 4) * 16);
    uint32_t b_off = (uint32_t)((wn * 32 + ((lane >> 4) << 3) + (lane & 7)) * SR +
                                ((lane >> 3) & 1) * 16);

#pragma unroll 1
    for (int k = 0; k < KIT; ++k) {
        CP_WAIT2();
        __syncthreads();
        if (k + 3 < KIT) load((k + 3) & 3, k + 3);
        else CP_COMMIT();

        uint32_t s0 = base + (uint32_t)(k & 3) * STAGE1;
#pragma unroll
        for (int ks = 0; ks < 4; ++ks) {          // 4 x K=16 steps
            uint32_t ra[2][4], rb[2][2][4];
#pragma unroll
            for (int mi = 0; mi < 2; ++mi)
                ldm_x4(ra[mi], s0 + a_off + (uint32_t)(mi * 16 * SR + ks * 32));
#pragma unroll
            for (int b = 0; b < 2; ++b)
#pragma unroll
                for (int nj = 0; nj < 2; ++nj)
                    ldm_x4(rb[b][nj], s0 + (uint32_t)((b + 1) * T128) + b_off +
                                      (uint32_t)(nj * 16 * SR + ks * 32));
#pragma unroll
            for (int b = 0; b < 2; ++b)
#pragma unroll
                for (int mi = 0; mi < 2; ++mi)
#pragma unroll
                    for (int ni = 0; ni < 4; ++ni)
                        mma16816(c[b][mi][ni], ra[mi],
                                 rb[b][ni >> 1][(ni & 1) * 2],
                                 rb[b][ni >> 1][(ni & 1) * 2 + 1]);
        }
    }

    // fused SiLU-gate epilogue -> g_act fp16
    int t0 = blockIdx.x * BM + wm * 32 + (lane >> 2);
    int h0 = blockIdx.y * 128 + wn * 32 + (lane & 3) * 2;
    __half* dst = g_act + (size_t)e * NT * NH;
#pragma unroll
    for (int mi = 0; mi < 2; ++mi)
#pragma unroll
        for (int ni = 0; ni < 4; ++ni) {
            int r = t0 + mi * 16, col = h0 + ni * 8;
            float* u = c[0][mi][ni];
            float* g = c[1][mi][ni];
            float a0 = g[0] * u[0] / (1.f + __expf(-u[0]));
            float a1 = g[1] * u[1] / (1.f + __expf(-u[1]));
            float a2 = g[2] * u[2] / (1.f + __expf(-u[2]));
            float a3 = g[3] * u[3] / (1.f + __expf(-u[3]));
            *reinterpret_cast<__half2*>(dst + (size_t)r * NH + col) =
                __floats2half2_rn(a0, a1);
            *reinterpret_cast<__half2*>(dst + (size_t)(r + 8) * NH + col) =
                __floats2half2_rn(a2, a3);
        }
}

// ---------------------------------------------------------------------------
// Phase 2: out = act @ w2^T   (K=4096, N=2048, fp32 out)
// ---------------------------------------------------------------------------
__global__ void __launch_bounds__(THREADS, 1) k_ffn2(float* __restrict__ out) {
    extern __shared__ __align__(128) char sm[];
    uint32_t base = smem_u32(sm);
    int tid = threadIdx.x, lane = tid & 31, wid = tid >> 5;
    int wm = wid >> 2, wn = wid & 3;
    int e = blockIdx.z;
    constexpr int KIT = NH / BK;  // 64
    constexpr uint32_t A_SM = T128;

    const __half* A = g_act + ((size_t)e * NT + blockIdx.y * BM) * NH;
    const __half* B = g_w2h + ((size_t)e * ND + blockIdx.x * 256) * NH;

    auto load = [&](int st, int kb) {
        uint32_t s0 = base + (uint32_t)st * STAGE2;
        int ko = kb * BK;
#pragma unroll
        for (int i = 0; i < 2; ++i) {             // A: 1024 chunks
            int id = tid + i * THREADS;
            int r = id >> 3, c = id & 7;
            cp16(s0 + (uint32_t)(r * SR + c * 16), A + (size_t)r * NH + ko + c * 8);
        }
#pragma unroll
        for (int i = 0; i < 4; ++i) {             // B: 2048 chunks (256 rows)
            int id = tid + i * THREADS;
            int r = id >> 3, c = id & 7;
            cp16(s0 + A_SM + (uint32_t)(r * SR + c * 16),
                 B + (size_t)r * NH + ko + c * 8);
        }
        CP_COMMIT();
    };

    load(0, 0);
    load(1, 1);
    load(2, 2);

    float c[2][8][4];
#pragma unroll
    for (int mi = 0; mi < 2; ++mi)
#pragma unroll
        for (int ni = 0; ni < 8; ++ni)
#pragma unroll
            for (int q = 0; q < 4; ++q) c[mi][ni][q] = 0.f;

    uint32_t a_off = (uint32_t)((wm * 32 + (lane & 15)) * SR + (lane >> 4) * 16);
    uint32_t b_off = A_SM +
        (uint32_t)((wn * 64 + ((lane >> 4) << 3) + (lane & 7)) * SR +
                   ((lane >> 3) & 1) * 16);

#pragma unroll 1
    for (int k = 0; k < KIT; ++k) {
        CP_WAIT2();
        __syncthreads();
        if (k + 3 < KIT) load((k + 3) & 3, k + 3);
        else CP_COMMIT();

        uint32_t s0 = base + (uint32_t)(k & 3) * STAGE2;
#pragma unroll
        for (int ks = 0; ks < 4; ++ks) {
            uint32_t ra[2][4], rb[4][4];
#pragma unroll
            for (int mi = 0; mi < 2; ++mi)
                ldm_x4(ra[mi], s0 + a_off + (uint32_t)(mi * 16 * SR + ks * 32));
#pragma unroll
            for (int nj = 0; nj < 4; ++nj)
                ldm_x4(rb[nj], s0 + b_off + (uint32_t)(nj * 16 * SR + ks * 32));
#pragma unroll
            for (int mi = 0; mi < 2; ++mi)
#pragma unroll
                for (int ni = 0; ni < 8; ++ni)
                    mma16816(c[mi][ni], ra[mi],
                             rb[ni >> 1][(ni & 1) * 2], rb[ni >> 1][(ni & 1) * 2 + 1]);
        }
    }

    int t0 = blockIdx.y * BM + wm * 32 + (lane >> 2);
    int n0 = blockIdx.x * 256 + wn * 64 + (lane & 3) * 2;
    float* C = out + (size_t)e * NT * ND;
#pragma unroll
    for (int mi = 0; mi < 2; ++mi)
#pragma unroll
        for (int ni = 0; ni < 8; ++ni) {
            int r = t0 + mi * 16, col = n0 + ni * 8;
            *reinterpret_cast<float2*>(C + (size_t)r * ND + col) =
                make_float2(c[mi][ni][0], c[mi][ni][1]);
            *reinterpret_cast<float2*>(C + (size_t)(r + 8) * ND + col) =
                make_float2(c[mi][ni][2], c[mi][ni][3]);
        }
}

// ---------------------------------------------------------------------------
// Launch (graph-capturable: kernel launches only)
// ---------------------------------------------------------------------------
extern "C" void kernel_launch(void* const* d_in, const int* in_sizes, int n_in,
                              void* d_out, int out_size) {
    const float* x  = (const float*)d_in[0];
    const float* w1 = (const float*)d_in[1];
    const float* w2 = (const float*)d_in[2];
    const float* w3 = (const float*)d_in[3];
    float* out = (float*)d_out;

    cudaFuncSetAttribute(k_ffn1, cudaFuncAttributeMaxDynamicSharedMemorySize, SMEM1);
    cudaFuncSetAttribute(k_ffn2, cudaFuncAttributeMaxDynamicSharedMemorySize, SMEM2);

    // prep: fp32 -> fp16 (+ w1 transpose to K-major)
    k_conv_x <<<16384, 256>>>(x);                       // E*T*D/4/256
    k_conv_w3<<<65536, 256>>>(w3);                      // E*D*H/4/256
    k_conv_w2<<<65536, 256>>>(w2);
    k_tr_w1<<<dim3(NH / 64, ND / 64, NE), 256>>>(w1);

    // fused up+gate+silu  (K=D=2048; grid x=M so waves share weight tiles)
    k_ffn1<<<dim3(NT / BM, NH / 128, NE), THREADS, SMEM1>>>();

    // down-proj           (K=H=4096, N=D=2048, fp32 out)
    k_ffn2<<<dim3(ND / 256, NT / BM, NE), THREADS, SMEM2>>>(out);
}

// round 8
// speedup vs baseline: 1.4187x; 1.1890x over previous
#include <cuda_runtime.h>
#include <cuda_fp16.h>
#include <cstdint>
#include <cstddef>

// ---------------------------------------------------------------------------
// Grouped SwiGLU FFN:  out = (silu(x@w1) * (x@w3^T)) @ w2^T   per expert
// E=8, T=1024, D=2048, H=4096, fp32 in/out.  sm_103 baseline ISA (mma.sync),
// warp-specialized producer/consumer pipeline. Producer completion is signaled
// via cp.async.commit_group + wait_group lag + regular mbarrier.arrive
// (cp.async.mbarrier.arrive default form is count-neutral -> deadlocked R7).
// ---------------------------------------------------------------------------
#define NE 8
#define NT 1024
#define ND 2048
#define NH 4096

static constexpr int BM = 128, BK = 64, STAGES = 4;
static constexpr int CONSUMERS = 512;                // 16 warps, 4x4
static constexpr int PRODUCERS = 64;                 // 2 warps
static constexpr int THREADS   = CONSUMERS + PRODUCERS;
// padded smem rows: 64 fp16 = 128 B data + 16 B pad = 144 B stride.
static constexpr uint32_t SR    = 144;
static constexpr uint32_t T128  = BM * SR;           // 18432 B per 128-row tile
static constexpr uint32_t STAGE = 3 * T128;          // 3 x 128-row tiles = 55296
static constexpr uint32_t SMEM  = STAGES * STAGE;    // 221184

// ---------------------------------------------------------------------------
// Scratch (__device__ bss — no runtime allocation)
// ---------------------------------------------------------------------------
__device__ __half g_x16[(size_t)NE * NT * ND];   //  32 MB  x fp16      [E,T,D]
__device__ __half g_w1t[(size_t)NE * NH * ND];   // 128 MB  w1^T fp16   [E,H,D]
__device__ __half g_w3h[(size_t)NE * NH * ND];   // 128 MB  w3 fp16     [E,H,D]
__device__ __half g_w2h[(size_t)NE * ND * NH];   // 128 MB  w2 fp16     [E,D,H]
__device__ __half g_act[(size_t)NE * NT * NH];   //  64 MB  silu(u)*g   [E,T,H]

// ---------------------------------------------------------------------------
// PTX helpers (baseline sm_80/sm_90 features only — no 'a' suffix)
// ---------------------------------------------------------------------------
__device__ __forceinline__ uint32_t smem_u32(const void* p) {
    return (uint32_t)__cvta_generic_to_shared(p);
}

__device__ __forceinline__ void cp16(uint32_t dst, const void* src) {
    asm volatile("cp.async.cg.shared.global [%0], [%1], 16;" ::"r"(dst), "l"(src)
                 : "memory");
}
#define CP_COMMIT() asm volatile("cp.async.commit_group;" ::: "memory")

__device__ __forceinline__ void mbar_init(uint32_t a, uint32_t cnt) {
    asm volatile("mbarrier.init.shared.b64 [%0], %1;" ::"r"(a), "r"(cnt) : "memory");
}
__device__ __forceinline__ void mbar_arrive(uint32_t a) {
    asm volatile("{\n\t.reg .b64 s;\n\tmbarrier.arrive.shared.b64 s, [%0];\n\t}"
                 ::"r"(a) : "memory");
}
__device__ __forceinline__ void mbar_wait(uint32_t a, uint32_t phase) {
    asm volatile(
        "{\n\t.reg .pred P;\n\t"
        "LW_%=:\n\t"
        "mbarrier.try_wait.parity.shared.b64 P, [%0], %1;\n\t"
        "@P bra.uni LD_%=;\n\t"
        "bra.uni LW_%=;\n\t"
        "LD_%=:\n\t}"
        ::"r"(a), "r"(phase) : "memory");
}

__device__ __forceinline__ void ldm_x4(uint32_t* r, uint32_t addr) {
    asm volatile("ldmatrix.sync.aligned.m8n8.x4.shared.b16 {%0,%1,%2,%3}, [%4];"
                 : "=r"(r[0]), "=r"(r[1]), "=r"(r[2]), "=r"(r[3])
                 : "r"(addr));
}

__device__ __forceinline__ void mma16816(float* c, const uint32_t* a,
                                         uint32_t b0, uint32_t b1) {
    asm volatile(
        "mma.sync.aligned.m16n8k16.row.col.f32.f16.f16.f32 "
        "{%0,%1,%2,%3}, {%4,%5,%6,%7}, {%8,%9}, {%0,%1,%2,%3};"
        : "+f"(c[0]), "+f"(c[1]), "+f"(c[2]), "+f"(c[3])
        : "r"(a[0]), "r"(a[1]), "r"(a[2]), "r"(a[3]), "r"(b0), "r"(b1));
}

// ---------------------------------------------------------------------------
// fp32 -> fp16 conversion / transpose prep kernels
// ---------------------------------------------------------------------------
__device__ __forceinline__ void conv_body(const float* __restrict__ src,
                                          __half* __restrict__ dst) {
    size_t i = (size_t)blockIdx.x * blockDim.x + threadIdx.x;
    float4 v = reinterpret_cast<const float4*>(src)[i];
    reinterpret_cast<__half2*>(dst)[2 * i]     = __floats2half2_rn(v.x, v.y);
    reinterpret_cast<__half2*>(dst)[2 * i + 1] = __floats2half2_rn(v.z, v.w);
}
__global__ void k_conv_x (const float* __restrict__ s) { conv_body(s, g_x16); }
__global__ void k_conv_w2(const float* __restrict__ s) { conv_body(s, g_w2h); }
__global__ void k_conv_w3(const float* __restrict__ s) { conv_body(s, g_w3h); }

// w1 [E,D,H] fp32 -> g_w1t [E,H,D] fp16, 64x64 tiles, 16B-wide ld/st
__global__ void __launch_bounds__(256) k_tr_w1(const float* __restrict__ w1) {
    __shared__ float t[64][65];
    int e = blockIdx.z, tid = threadIdx.x;
    int h0 = blockIdx.x * 64, d0 = blockIdx.y * 64;
    const float* src = w1 + ((size_t)e * ND + d0) * NH + h0;
#pragma unroll
    for (int i = 0; i < 4; ++i) {
        int u = tid + i * 256;
        int r = u >> 4, c4 = u & 15;
        float4 v = *reinterpret_cast<const float4*>(src + (size_t)r * NH + c4 * 4);
        t[r][c4 * 4 + 0] = v.x; t[r][c4 * 4 + 1] = v.y;
        t[r][c4 * 4 + 2] = v.z; t[r][c4 * 4 + 3] = v.w;
    }
    __syncthreads();
    __half* dst = g_w1t + ((size_t)e * NH + h0) * ND + d0;
#pragma unroll
    for (int i = 0; i < 2; ++i) {
        int u = tid + i * 256;
        int hr = u >> 3, dc = (u & 7) * 8;
        __half2 h2[4];
#pragma unroll
        for (int j = 0; j < 4; ++j)
            h2[j] = __floats2half2_rn(t[dc + 2 * j][hr], t[dc + 2 * j + 1][hr]);
        *reinterpret_cast<uint4*>(dst + (size_t)hr * ND + dc) =
            *reinterpret_cast<uint4*>(h2);
    }
}

// ---------------------------------------------------------------------------
// Producer fill: 3 x 128-row tiles per stage, 64 producer threads.
// ---------------------------------------------------------------------------
template <int STRIDE>
__device__ __forceinline__ void fill_stage(uint32_t s0, const __half* t0,
                                           const __half* t1, const __half* t2,
                                           int ko, int p) {
    const __half* bases[3] = {t0, t1, t2};
#pragma unroll
    for (int t = 0; t < 3; ++t) {
        const __half* g = bases[t] + ko;
        uint32_t sd = s0 + (uint32_t)t * T128;
#pragma unroll
        for (int i = 0; i < 16; ++i) {               // 1024 chunks / 64 thr
            int id = p + i * 64;
            int r = id >> 3, c = id & 7;
            cp16(sd + (uint32_t)(r * SR + c * 16), g + (size_t)r * STRIDE + c * 8);
        }
    }
}

// barriers in static smem
struct Bars { uint64_t full[STAGES]; uint64_t empty[STAGES]; };

__device__ __forceinline__ void bars_init(Bars* b, int tid) {
    if (tid == 0) {
#pragma unroll
        for (int s = 0; s < STAGES; ++s) {
            mbar_init(smem_u32(&b->full[s]), PRODUCERS);
            mbar_init(smem_u32(&b->empty[s]), CONSUMERS);
        }
    }
    __syncthreads();
}

// Producer loop: commit one cp.async group per stage; signal full[k-2] once
// wait_group 2 guarantees that group has landed. Drain the last two at exit.
template <int STRIDE, int KIT>
__device__ __forceinline__ void producer_loop(Bars* bars, uint32_t base,
                                              const __half* t0, const __half* t1,
                                              const __half* t2, int p) {
#pragma unroll 1
    for (int k = 0; k < KIT; ++k) {
        int s = k & (STAGES - 1);
        if (k >= STAGES) mbar_wait(smem_u32(&bars->empty[s]), ((k >> 2) - 1) & 1);
        fill_stage<STRIDE>(base + (uint32_t)s * STAGE, t0, t1, t2, k * BK, p);
        CP_COMMIT();
        if (k >= 2) {
            asm volatile("cp.async.wait_group 2;" ::: "memory");
            mbar_arrive(smem_u32(&bars->full[(k - 2) & (STAGES - 1)]));
        }
    }
    asm volatile("cp.async.wait_group 1;" ::: "memory");
    mbar_arrive(smem_u32(&bars->full[(KIT - 2) & (STAGES - 1)]));
    asm volatile("cp.async.wait_group 0;" ::: "memory");
    mbar_arrive(smem_u32(&bars->full[(KIT - 1) & (STAGES - 1)]));
}

// ---------------------------------------------------------------------------
// Phase 1 (fused): u = x@w1t^T, g = x@w3^T, act = silu(u)*g  -> g_act fp16
// ---------------------------------------------------------------------------
__global__ void __launch_bounds__(THREADS, 1) k_ffn1() {
    extern __shared__ __align__(128) char sm[];
    __shared__ Bars bars;
    uint32_t base = smem_u32(sm);
    int tid = threadIdx.x, lane = tid & 31, wid = tid >> 5;
    int e = blockIdx.z;
    constexpr int KIT = ND / BK;  // 32

    const __half* A  = g_x16 + ((size_t)e * NT + blockIdx.x * BM) * ND;
    const __half* B1 = g_w1t + ((size_t)e * NH + blockIdx.y * 128) * ND;
    const __half* B2 = g_w3h + ((size_t)e * NH + blockIdx.y * 128) * ND;

    bars_init(&bars, tid);

    if (tid >= CONSUMERS) {                           // ---- producer warps
        producer_loop<ND, KIT>(&bars, base, A, B1, B2, tid - CONSUMERS);
        return;
    }

    // ---- consumer warps (4x4 grid, warp tile 32x32 per B operand)
    int wm = wid >> 2, wn = wid & 3;
    float c[2][2][4][4];
#pragma unroll
    for (int b = 0; b < 2; ++b)
#pragma unroll
        for (int mi = 0; mi < 2; ++mi)
#pragma unroll
            for (int ni = 0; ni < 4; ++ni)
#pragma unroll
                for (int q = 0; q < 4; ++q) c[b][mi][ni][q] = 0.f;

    uint32_t a_off = (uint32_t)((wm * 32 + (lane & 15)) * SR + (lane >> 4) * 16);
    uint32_t b_off = (uint32_t)((wn * 32 + ((lane >> 4) << 3) + (lane & 7)) * SR +
                                ((lane >> 3) & 1) * 16);

#pragma unroll 1
    for (int k = 0; k < KIT; ++k) {
        int s = k & (STAGES - 1);
        mbar_wait(smem_u32(&bars.full[s]), (k >> 2) & 1);
        uint32_t s0 = base + (uint32_t)s * STAGE;
#pragma unroll
        for (int ks = 0; ks < 4; ++ks) {              // 4 x K=16 steps
            uint32_t ra[2][4], rb[2][2][4];
#pragma unroll
            for (int mi = 0; mi < 2; ++mi)
                ldm_x4(ra[mi], s0 + a_off + (uint32_t)(mi * 16 * SR + ks * 32));
#pragma unroll
            for (int b = 0; b < 2; ++b)
#pragma unroll
                for (int nj = 0; nj < 2; ++nj)
                    ldm_x4(rb[b][nj], s0 + (uint32_t)((b + 1) * T128) + b_off +
                                      (uint32_t)(nj * 16 * SR + ks * 32));
#pragma unroll
            for (int b = 0; b < 2; ++b)
#pragma unroll
                for (int mi = 0; mi < 2; ++mi)
#pragma unroll
                    for (int ni = 0; ni < 4; ++ni)
                        mma16816(c[b][mi][ni], ra[mi],
                                 rb[b][ni >> 1][(ni & 1) * 2],
                                 rb[b][ni >> 1][(ni & 1) * 2 + 1]);
        }
        mbar_arrive(smem_u32(&bars.empty[s]));
    }

    // fused SiLU-gate epilogue -> g_act fp16
    int t0 = blockIdx.x * BM + wm * 32 + (lane >> 2);
    int h0 = blockIdx.y * 128 + wn * 32 + (lane & 3) * 2;
    __half* dst = g_act + (size_t)e * NT * NH;
#pragma unroll
    for (int mi = 0; mi < 2; ++mi)
#pragma unroll
        for (int ni = 0; ni < 4; ++ni) {
            int r = t0 + mi * 16, col = h0 + ni * 8;
            float* u = c[0][mi][ni];
            float* g = c[1][mi][ni];
            float a0 = g[0] * u[0] / (1.f + __expf(-u[0]));
            float a1 = g[1] * u[1] / (1.f + __expf(-u[1]));
            float a2 = g[2] * u[2] / (1.f + __expf(-u[2]));
            float a3 = g[3] * u[3] / (1.f + __expf(-u[3]));
            *reinterpret_cast<__half2*>(dst + (size_t)r * NH + col) =
                __floats2half2_rn(a0, a1);
            *reinterpret_cast<__half2*>(dst + (size_t)(r + 8) * NH + col) =
                __floats2half2_rn(a2, a3);
        }
}

// ---------------------------------------------------------------------------
// Phase 2: out = act @ w2^T   (K=4096, N=2048, fp32 out)
// ---------------------------------------------------------------------------
__global__ void __launch_bounds__(THREADS, 1) k_ffn2(float* __restrict__ out) {
    extern __shared__ __align__(128) char sm[];
    __shared__ Bars bars;
    uint32_t base = smem_u32(sm);
    int tid = threadIdx.x, lane = tid & 31, wid = tid >> 5;
    int e = blockIdx.z;
    constexpr int KIT = NH / BK;  // 64

    const __half* A = g_act + ((size_t)e * NT + blockIdx.y * BM) * NH;
    const __half* B = g_w2h + ((size_t)e * ND + blockIdx.x * 256) * NH;

    bars_init(&bars, tid);

    if (tid >= CONSUMERS) {                           // ---- producer warps
        producer_loop<NH, KIT>(&bars, base, A, B, B + (size_t)128 * NH,
                               tid - CONSUMERS);
        return;
    }

    // ---- consumer warps (4x4 grid, warp tile 32x64)
    int wm = wid >> 2, wn = wid & 3;
    float c[2][8][4];
#pragma unroll
    for (int mi = 0; mi < 2; ++mi)
#pragma unroll
        for (int ni = 0; ni < 8; ++ni)
#pragma unroll
            for (int q = 0; q < 4; ++q) c[mi][ni][q] = 0.f;

    uint32_t a_off = (uint32_t)((wm * 32 + (lane & 15)) * SR + (lane >> 4) * 16);
    uint32_t b_off = T128 +                            // B rows 0..255 contiguous
        (uint32_t)((wn * 64 + ((lane >> 4) << 3) + (lane & 7)) * SR +
                   ((lane >> 3) & 1) * 16);

#pragma unroll 1
    for (int k = 0; k < KIT; ++k) {
        int s = k & (STAGES - 1);
        mbar_wait(smem_u32(&bars.full[s]), (k >> 2) & 1);
        uint32_t s0 = base + (uint32_t)s * STAGE;
#pragma unroll
        for (int ks = 0; ks < 4; ++ks) {
            uint32_t ra[2][4], rb[4][4];
#pragma unroll
            for (int mi = 0; mi < 2; ++mi)
                ldm_x4(ra[mi], s0 + a_off + (uint32_t)(mi * 16 * SR + ks * 32));
#pragma unroll
            for (int nj = 0; nj < 4; ++nj)
                ldm_x4(rb[nj], s0 + b_off + (uint32_t)(nj * 16 * SR + ks * 32));
#pragma unroll
            for (int mi = 0; mi < 2; ++mi)
#pragma unroll
                for (int ni = 0; ni < 8; ++ni)
                    mma16816(c[mi][ni], ra[mi],
                             rb[ni >> 1][(ni & 1) * 2], rb[ni >> 1][(ni & 1) * 2 + 1]);
        }
        mbar_arrive(smem_u32(&bars.empty[s]));
    }

    int t0 = blockIdx.y * BM + wm * 32 + (lane >> 2);
    int n0 = blockIdx.x * 256 + wn * 64 + (lane & 3) * 2;
    float* C = out + (size_t)e * NT * ND;
#pragma unroll
    for (int mi = 0; mi < 2; ++mi)
#pragma unroll
        for (int ni = 0; ni < 8; ++ni) {
            int r = t0 + mi * 16, col = n0 + ni * 8;
            *reinterpret_cast<float2*>(C + (size_t)r * ND + col) =
                make_float2(c[mi][ni][0], c[mi][ni][1]);
            *reinterpret_cast<float2*>(C + (size_t)(r + 8) * ND + col) =
                make_float2(c[mi][ni][2], c[mi][ni][3]);
        }
}

// ---------------------------------------------------------------------------
// Launch (graph-capturable: kernel launches only)
// ---------------------------------------------------------------------------
extern "C" void kernel_launch(void* const* d_in, const int* in_sizes, int n_in,
                              void* d_out, int out_size) {
    const float* x  = (const float*)d_in[0];
    const float* w1 = (const float*)d_in[1];
    const float* w2 = (const float*)d_in[2];
    const float* w3 = (const float*)d_in[3];
    float* out = (float*)d_out;

    cudaFuncSetAttribute(k_ffn1, cudaFuncAttributeMaxDynamicSharedMemorySize, SMEM);
    cudaFuncSetAttribute(k_ffn2, cudaFuncAttributeMaxDynamicSharedMemorySize, SMEM);

    // prep: fp32 -> fp16 (+ w1 transpose to K-major)
    k_conv_x <<<16384, 256>>>(x);                       // E*T*D/4/256
    k_conv_w3<<<65536, 256>>>(w3);                      // E*D*H/4/256
    k_conv_w2<<<65536, 256>>>(w2);
    k_tr_w1<<<dim3(NH / 64, ND / 64, NE), 256>>>(w1);

    // fused up+gate+silu  (K=D=2048; x = M-tile, y = N-tile)
    k_ffn1<<<dim3(NT / BM, NH / 128, NE), THREADS, SMEM>>>();

    // down-proj           (K=H=4096, N=D=2048, fp32 out)
    k_ffn2<<<dim3(ND / 256, NT / BM, NE), THREADS, SMEM>>>(out);
}

// round 9
// speedup vs baseline: 1.4205x; 1.0013x over previous
#include <cuda_runtime.h>
#include <cuda_fp16.h>
#include <cstdint>
#include <cstddef>

// ---------------------------------------------------------------------------
// Grouped SwiGLU FFN:  out = (silu(x@w1) * (x@w3^T)) @ w2^T   per expert
// E=8, T=1024, D=2048, H=4096, fp32 in/out.  sm_103 baseline ISA (mma.sync),
// warp-specialized producer/consumer pipeline, 64x64 consumer warp tiles.
// ---------------------------------------------------------------------------
#define NE 8
#define NT 1024
#define ND 2048
#define NH 4096

static constexpr int BM = 128, BK = 64, STAGES = 4;
static constexpr int CONSUMERS = 256;                // 8 warps, 2x4, 64x64 tiles
static constexpr int PRODUCERS = 64;                 // 2 warps
static constexpr int THREADS   = CONSUMERS + PRODUCERS;  // 320
// padded smem rows: 64 fp16 = 128 B data + 16 B pad = 144 B stride.
static constexpr uint32_t SR    = 144;
static constexpr uint32_t T128  = BM * SR;           // 18432 B per 128-row tile
static constexpr uint32_t STAGE = 3 * T128;          // 3 x 128-row tiles = 55296
static constexpr uint32_t SMEM  = STAGES * STAGE;    // 221184

// ---------------------------------------------------------------------------
// Scratch (__device__ bss — no runtime allocation)
// ---------------------------------------------------------------------------
__device__ __half g_x16[(size_t)NE * NT * ND];   //  32 MB  x fp16      [E,T,D]
__device__ __half g_w1t[(size_t)NE * NH * ND];   // 128 MB  w1^T fp16   [E,H,D]
__device__ __half g_w3h[(size_t)NE * NH * ND];   // 128 MB  w3 fp16     [E,H,D]
__device__ __half g_w2h[(size_t)NE * ND * NH];   // 128 MB  w2 fp16     [E,D,H]
__device__ __half g_act[(size_t)NE * NT * NH];   //  64 MB  silu(u)*g   [E,T,H]

// ---------------------------------------------------------------------------
// PTX helpers (baseline sm_80/sm_90 features only — no 'a' suffix)
// ---------------------------------------------------------------------------
__device__ __forceinline__ uint32_t smem_u32(const void* p) {
    return (uint32_t)__cvta_generic_to_shared(p);
}

__device__ __forceinline__ void cp16(uint32_t dst, const void* src) {
    asm volatile("cp.async.cg.shared.global [%0], [%1], 16;" ::"r"(dst), "l"(src)
                 : "memory");
}
#define CP_COMMIT() asm volatile("cp.async.commit_group;" ::: "memory")

__device__ __forceinline__ void mbar_init(uint32_t a, uint32_t cnt) {
    asm volatile("mbarrier.init.shared.b64 [%0], %1;" ::"r"(a), "r"(cnt) : "memory");
}
__device__ __forceinline__ void mbar_arrive(uint32_t a) {
    asm volatile("{\n\t.reg .b64 s;\n\tmbarrier.arrive.shared.b64 s, [%0];\n\t}"
                 ::"r"(a) : "memory");
}
__device__ __forceinline__ void mbar_wait(uint32_t a, uint32_t phase) {
    asm volatile(
        "{\n\t.reg .pred P;\n\t"
        "LW_%=:\n\t"
        "mbarrier.try_wait.parity.shared.b64 P, [%0], %1;\n\t"
        "@P bra.uni LD_%=;\n\t"
        "bra.uni LW_%=;\n\t"
        "LD_%=:\n\t}"
        ::"r"(a), "r"(phase) : "memory");
}

__device__ __forceinline__ void ldm_x4(uint32_t* r, uint32_t addr) {
    asm volatile("ldmatrix.sync.aligned.m8n8.x4.shared.b16 {%0,%1,%2,%3}, [%4];"
                 : "=r"(r[0]), "=r"(r[1]), "=r"(r[2]), "=r"(r[3])
                 : "r"(addr));
}

__device__ __forceinline__ void mma16816(float* c, const uint32_t* a,
                                         uint32_t b0, uint32_t b1) {
    asm volatile(
        "mma.sync.aligned.m16n8k16.row.col.f32.f16.f16.f32 "
        "{%0,%1,%2,%3}, {%4,%5,%6,%7}, {%8,%9}, {%0,%1,%2,%3};"
        : "+f"(c[0]), "+f"(c[1]), "+f"(c[2]), "+f"(c[3])
        : "r"(a[0]), "r"(a[1]), "r"(a[2]), "r"(a[3]), "r"(b0), "r"(b1));
}

// ---------------------------------------------------------------------------
// fp32 -> fp16 conversion / transpose prep kernels
// ---------------------------------------------------------------------------
__device__ __forceinline__ void conv_body(const float* __restrict__ src,
                                          __half* __restrict__ dst) {
    size_t i = (size_t)blockIdx.x * blockDim.x + threadIdx.x;
    float4 v = reinterpret_cast<const float4*>(src)[i];
    reinterpret_cast<__half2*>(dst)[2 * i]     = __floats2half2_rn(v.x, v.y);
    reinterpret_cast<__half2*>(dst)[2 * i + 1] = __floats2half2_rn(v.z, v.w);
}
__global__ void k_conv_x (const float* __restrict__ s) { conv_body(s, g_x16); }
__global__ void k_conv_w2(const float* __restrict__ s) { conv_body(s, g_w2h); }
__global__ void k_conv_w3(const float* __restrict__ s) { conv_body(s, g_w3h); }

// w1 [E,D,H] fp32 -> g_w1t [E,H,D] fp16, 64x64 tiles, 16B-wide ld/st
__global__ void __launch_bounds__(256) k_tr_w1(const float* __restrict__ w1) {
    __shared__ float t[64][65];
    int e = blockIdx.z, tid = threadIdx.x;
    int h0 = blockIdx.x * 64, d0 = blockIdx.y * 64;
    const float* src = w1 + ((size_t)e * ND + d0) * NH + h0;
#pragma unroll
    for (int i = 0; i < 4; ++i) {
        int u = tid + i * 256;
        int r = u >> 4, c4 = u & 15;
        float4 v = *reinterpret_cast<const float4*>(src + (size_t)r * NH + c4 * 4);
        t[r][c4 * 4 + 0] = v.x; t[r][c4 * 4 + 1] = v.y;
        t[r][c4 * 4 + 2] = v.z; t[r][c4 * 4 + 3] = v.w;
    }
    __syncthreads();
    __half* dst = g_w1t + ((size_t)e * NH + h0) * ND + d0;
#pragma unroll
    for (int i = 0; i < 2; ++i) {
        int u = tid + i * 256;
        int hr = u >> 3, dc = (u & 7) * 8;
        __half2 h2[4];
#pragma unroll
        for (int j = 0; j < 4; ++j)
            h2[j] = __floats2half2_rn(t[dc + 2 * j][hr], t[dc + 2 * j + 1][hr]);
        *reinterpret_cast<uint4*>(dst + (size_t)hr * ND + dc) =
            *reinterpret_cast<uint4*>(h2);
    }
}

// ---------------------------------------------------------------------------
// Producer fill: 3 x 128-row tiles per stage, 64 producer threads.
// ---------------------------------------------------------------------------
template <int STRIDE>
__device__ __forceinline__ void fill_stage(uint32_t s0, const __half* t0,
                                           const __half* t1, const __half* t2,
                                           int ko, int p) {
    const __half* bases[3] = {t0, t1, t2};
#pragma unroll
    for (int t = 0; t < 3; ++t) {
        const __half* g = bases[t] + ko;
        uint32_t sd = s0 + (uint32_t)t * T128;
#pragma unroll
        for (int i = 0; i < 16; ++i) {               // 1024 chunks / 64 thr
            int id = p + i * 64;
            int r = id >> 3, c = id & 7;
            cp16(sd + (uint32_t)(r * SR + c * 16), g + (size_t)r * STRIDE + c * 8);
        }
    }
}

// barriers in static smem
struct Bars { uint64_t full[STAGES]; uint64_t empty[STAGES]; };

__device__ __forceinline__ void bars_init(Bars* b, int tid) {
    if (tid == 0) {
#pragma unroll
        for (int s = 0; s < STAGES; ++s) {
            mbar_init(smem_u32(&b->full[s]), PRODUCERS);
            mbar_init(smem_u32(&b->empty[s]), CONSUMERS);
        }
    }
    __syncthreads();
}

// Producer loop: commit one cp.async group per stage; signal full[k-2] once
// wait_group 2 guarantees that group has landed. Drain the last two at exit.
template <int STRIDE, int KIT>
__device__ __forceinline__ void producer_loop(Bars* bars, uint32_t base,
                                              const __half* t0, const __half* t1,
                                              const __half* t2, int p) {
#pragma unroll 1
    for (int k = 0; k < KIT; ++k) {
        int s = k & (STAGES - 1);
        if (k >= STAGES) mbar_wait(smem_u32(&bars->empty[s]), ((k >> 2) - 1) & 1);
        fill_stage<STRIDE>(base + (uint32_t)s * STAGE, t0, t1, t2, k * BK, p);
        CP_COMMIT();
        if (k >= 2) {
            asm volatile("cp.async.wait_group 2;" ::: "memory");
            mbar_arrive(smem_u32(&bars->full[(k - 2) & (STAGES - 1)]));
        }
    }
    asm volatile("cp.async.wait_group 1;" ::: "memory");
    mbar_arrive(smem_u32(&bars->full[(KIT - 2) & (STAGES - 1)]));
    asm volatile("cp.async.wait_group 0;" ::: "memory");
    mbar_arrive(smem_u32(&bars->full[(KIT - 1) & (STAGES - 1)]));
}

// ---------------------------------------------------------------------------
// Phase 1 (fused): u = x@w1t^T, g = x@w3^T, act = silu(u)*g  -> g_act fp16
// 8 consumer warps (2x4): warp tile 64 (M) x 32 (N) per B operand.
// ---------------------------------------------------------------------------
__global__ void __launch_bounds__(THREADS, 1) k_ffn1() {
    extern __shared__ __align__(128) char sm[];
    __shared__ Bars bars;
    uint32_t base = smem_u32(sm);
    int tid = threadIdx.x, lane = tid & 31, wid = tid >> 5;
    int e = blockIdx.z;
    constexpr int KIT = ND / BK;  // 32

    const __half* A  = g_x16 + ((size_t)e * NT + blockIdx.x * BM) * ND;
    const __half* B1 = g_w1t + ((size_t)e * NH + blockIdx.y * 128) * ND;
    const __half* B2 = g_w3h + ((size_t)e * NH + blockIdx.y * 128) * ND;

    bars_init(&bars, tid);

    if (tid >= CONSUMERS) {                           // ---- producer warps
        producer_loop<ND, KIT>(&bars, base, A, B1, B2, tid - CONSUMERS);
        return;
    }

    // ---- consumer warps: wm in {0,1} (64 M-rows), wn in {0..3} (32 N-cols)
    int wm = wid >> 2, wn = wid & 3;
    float c[2][4][4][4];                              // [B][mi][ni][frag]
#pragma unroll
    for (int b = 0; b < 2; ++b)
#pragma unroll
        for (int mi = 0; mi < 4; ++mi)
#pragma unroll
            for (int ni = 0; ni < 4; ++ni)
#pragma unroll
                for (int q = 0; q < 4; ++q) c[b][mi][ni][q] = 0.f;

    uint32_t a_off = (uint32_t)((wm * 64 + (lane & 15)) * SR + (lane >> 4) * 16);
    uint32_t b_off = (uint32_t)((wn * 32 + ((lane >> 4) << 3) + (lane & 7)) * SR +
                                ((lane >> 3) & 1) * 16);

#pragma unroll 1
    for (int k = 0; k < KIT; ++k) {
        int s = k & (STAGES - 1);
        mbar_wait(smem_u32(&bars.full[s]), (k >> 2) & 1);
        uint32_t s0 = base + (uint32_t)s * STAGE;
#pragma unroll
        for (int ks = 0; ks < 4; ++ks) {              // 4 x K=16 steps
            uint32_t ra[4][4], rb[2][2][4];
#pragma unroll
            for (int mi = 0; mi < 4; ++mi)
                ldm_x4(ra[mi], s0 + a_off + (uint32_t)(mi * 16 * SR + ks * 32));
#pragma unroll
            for (int b = 0; b < 2; ++b)
#pragma unroll
                for (int nj = 0; nj < 2; ++nj)
                    ldm_x4(rb[b][nj], s0 + (uint32_t)((b + 1) * T128) + b_off +
                                      (uint32_t)(nj * 16 * SR + ks * 32));
#pragma unroll
            for (int b = 0; b < 2; ++b)
#pragma unroll
                for (int mi = 0; mi < 4; ++mi)
#pragma unroll
                    for (int ni = 0; ni < 4; ++ni)
                        mma16816(c[b][mi][ni], ra[mi],
                                 rb[b][ni >> 1][(ni & 1) * 2],
                                 rb[b][ni >> 1][(ni & 1) * 2 + 1]);
        }
        mbar_arrive(smem_u32(&bars.empty[s]));
    }

    // fused SiLU-gate epilogue -> g_act fp16
    int t0 = blockIdx.x * BM + wm * 64 + (lane >> 2);
    int h0 = blockIdx.y * 128 + wn * 32 + (lane & 3) * 2;
    __half* dst = g_act + (size_t)e * NT * NH;
#pragma unroll
    for (int mi = 0; mi < 4; ++mi)
#pragma unroll
        for (int ni = 0; ni < 4; ++ni) {
            int r = t0 + mi * 16, col = h0 + ni * 8;
            float* u = c[0][mi][ni];
            float* g = c[1][mi][ni];
            float a0 = g[0] * u[0] / (1.f + __expf(-u[0]));
            float a1 = g[1] * u[1] / (1.f + __expf(-u[1]));
            float a2 = g[2] * u[2] / (1.f + __expf(-u[2]));
            float a3 = g[3] * u[3] / (1.f + __expf(-u[3]));
            *reinterpret_cast<__half2*>(dst + (size_t)r * NH + col) =
                __floats2half2_rn(a0, a1);
            *reinterpret_cast<__half2*>(dst + (size_t)(r + 8) * NH + col) =
                __floats2half2_rn(a2, a3);
        }
}

// ---------------------------------------------------------------------------
// Phase 2: out = act @ w2^T   (K=4096, N=2048, fp32 out)
// 8 consumer warps (2x4): warp tile 64 x 64.
// ---------------------------------------------------------------------------
__global__ void __launch_bounds__(THREADS, 1) k_ffn2(float* __restrict__ out) {
    extern __shared__ __align__(128) char sm[];
    __shared__ Bars bars;
    uint32_t base = smem_u32(sm);
    int tid = threadIdx.x, lane = tid & 31, wid = tid >> 5;
    int e = blockIdx.z;
    constexpr int KIT = NH / BK;  // 64

    const __half* A = g_act + ((size_t)e * NT + blockIdx.y * BM) * NH;
    const __half* B = g_w2h + ((size_t)e * ND + blockIdx.x * 256) * NH;

    bars_init(&bars, tid);

    if (tid >= CONSUMERS) {                           // ---- producer warps
        producer_loop<NH, KIT>(&bars, base, A, B, B + (size_t)128 * NH,
                               tid - CONSUMERS);
        return;
    }

    // ---- consumer warps: wm in {0,1}, wn in {0..3} (64-col slices)
    int wm = wid >> 2, wn = wid & 3;
    float c[4][8][4];
#pragma unroll
    for (int mi = 0; mi < 4; ++mi)
#pragma unroll
        for (int ni = 0; ni < 8; ++ni)
#pragma unroll
            for (int q = 0; q < 4; ++q) c[mi][ni][q] = 0.f;

    uint32_t a_off = (uint32_t)((wm * 64 + (lane & 15)) * SR + (lane >> 4) * 16);
    uint32_t b_off = T128 +                            // B rows 0..255 contiguous
        (uint32_t)((wn * 64 + ((lane >> 4) << 3) + (lane & 7)) * SR +
                   ((lane >> 3) & 1) * 16);

#pragma unroll 1
    for (int k = 0; k < KIT; ++k) {
        int s = k & (STAGES - 1);
        mbar_wait(smem_u32(&bars.full[s]), (k >> 2) & 1);
        uint32_t s0 = base + (uint32_t)s * STAGE;
#pragma unroll
        for (int ks = 0; ks < 4; ++ks) {
            uint32_t ra[4][4], rb[4][4];
#pragma unroll
            for (int mi = 0; mi < 4; ++mi)
                ldm_x4(ra[mi], s0 + a_off + (uint32_t)(mi * 16 * SR + ks * 32));
#pragma unroll
            for (int nj = 0; nj < 4; ++nj)
                ldm_x4(rb[nj], s0 + b_off + (uint32_t)(nj * 16 * SR + ks * 32));
#pragma unroll
            for (int mi = 0; mi < 4; ++mi)
#pragma unroll
                for (int ni = 0; ni < 8; ++ni)
                    mma16816(c[mi][ni], ra[mi],
                             rb[ni >> 1][(ni & 1) * 2], rb[ni >> 1][(ni & 1) * 2 + 1]);
        }
        mbar_arrive(smem_u32(&bars.empty[s]));
    }

    int t0 = blockIdx.y * BM + wm * 64 + (lane >> 2);
    int n0 = blockIdx.x * 256 + wn * 64 + (lane & 3) * 2;
    float* C = out + (size_t)e * NT * ND;
#pragma unroll
    for (int mi = 0; mi < 4; ++mi)
#pragma unroll
        for (int ni = 0; ni < 8; ++ni) {
            int r = t0 + mi * 16, col = n0 + ni * 8;
            *reinterpret_cast<float2*>(C + (size_t)r * ND + col) =
                make_float2(c[mi][ni][0], c[mi][ni][1]);
            *reinterpret_cast<float2*>(C + (size_t)(r + 8) * ND + col) =
                make_float2(c[mi][ni][2], c[mi][ni][3]);
        }
}

// ---------------------------------------------------------------------------
// Launch (graph-capturable: kernel launches only)
// ---------------------------------------------------------------------------
extern "C" void kernel_launch(void* const* d_in, const int* in_sizes, int n_in,
                              void* d_out, int out_size) {
    const float* x  = (const float*)d_in[0];
    const float* w1 = (const float*)d_in[1];
    const float* w2 = (const float*)d_in[2];
    const float* w3 = (const float*)d_in[3];
    float* out = (float*)d_out;

    cudaFuncSetAttribute(k_ffn1, cudaFuncAttributeMaxDynamicSharedMemorySize, SMEM);
    cudaFuncSetAttribute(k_ffn2, cudaFuncAttributeMaxDynamicSharedMemorySize, SMEM);

    // prep: fp32 -> fp16 (+ w1 transpose to K-major)
    k_conv_x <<<16384, 256>>>(x);                       // E*T*D/4/256
    k_conv_w3<<<65536, 256>>>(w3);                      // E*D*H/4/256
    k_conv_w2<<<65536, 256>>>(w2);
    k_tr_w1<<<dim3(NH / 64, ND / 64, NE), 256>>>(w1);

    // fused up+gate+silu  (K=D=2048; x = M-tile, y = N-tile)
    k_ffn1<<<dim3(NT / BM, NH / 128, NE), THREADS, SMEM>>>();

    // down-proj           (K=H=4096, N=D=2048, fp32 out)
    k_ffn2<<<dim3(ND / 256, NT / BM, NE), THREADS, SMEM>>>(out);
}